// round 2
// baseline (speedup 1.0000x reference)
#include <cuda_runtime.h>

// SliceLSTM persistent kernel: B=64, T=512, S=4, DIN=64, H=128, HTOT=512.
// One persistent kernel, 128 CTAs x 256 threads (all co-resident on 148 SMs),
// global ticket barrier between phases. Weights live in SMEM for all steps.
// Cross-CTA state goes through L2 only (__ldcg/__stcg).

#define BB    64
#define TSEQ  512
#define NCTA  128
#define NTHR  256
#define LDB   68          // padded b-stride for transposed activation staging

#define OFF_W1 0          // 192*16 floats
#define OFF_B1 3072       // 16
#define OFF_W2 3088       // 64*128
#define OFF_A  11280      // 192*LDB
#define SMEM_FLOATS 24336 // 97344 bytes

__device__ float g_h[BB * 512];            // hidden state  [b][c]
__device__ float g_act[4 * BB * 512];      // stage-1 activated gates [gate][b][c]
__device__ float g_part[NCTA * BB * 128];  // connector partials [cta][b][c_local]
__device__ unsigned long long g_bar;       // monotonic ticket counter

static __device__ __forceinline__ unsigned long long pk2(float lo, float hi) {
    unsigned long long r;
    asm("mov.b64 %0, {%1, %2};" : "=l"(r) : "f"(lo), "f"(hi));
    return r;
}
static __device__ __forceinline__ void unp2(unsigned long long v, float& lo, float& hi) {
    asm("mov.b64 {%0, %1}, %2;" : "=f"(lo), "=f"(hi) : "l"(v));
}
static __device__ __forceinline__ void fma2(unsigned long long& d,
                                            unsigned long long a, unsigned long long b) {
    asm("fma.rn.f32x2 %0, %1, %2, %0;" : "+l"(d) : "l"(a), "l"(b));
}
static __device__ __forceinline__ float sigf(float x)  { return 1.0f / (1.0f + __expf(-x)); }
static __device__ __forceinline__ float tanhe(float x) {
    float e = __expf(2.0f * x);          // e->inf => 1, e->0 => -1 : correct saturation
    return 1.0f - 2.0f / (e + 1.0f);
}

// Global ticket barrier over all 128 resident CTAs. Counter is monotonic and
// every launch adds a multiple of NCTA, so graph replays stay consistent.
static __device__ __forceinline__ void gbar() {
    __threadfence();
    __syncthreads();
    if (threadIdx.x == 0) {
        unsigned long long tk = atomicAdd(&g_bar, 1ULL);
        unsigned long long goal = (tk / NCTA) * NCTA + NCTA;
        while (*((volatile unsigned long long*)&g_bar) < goal) {
            __nanosleep(32);
        }
    }
    __syncthreads();
}

__global__ void __launch_bounds__(NTHR, 1)
slstm_kernel(const float* __restrict__ x,       // (64, 512, 256)
             const float* __restrict__ Ws,      // (4, 64, 512)
             const float* __restrict__ Us,      // (4, 128, 512)
             const float* __restrict__ biases,  // (4, 512)
             const float* __restrict__ Wc,      // (512, 2048)
             const float* __restrict__ bc,      // (2048,)
             float* __restrict__ out)           // hseq | h_t | c_t
{
    extern __shared__ float sm[];
    float* sW1 = sm + OFF_W1;
    float* sB1 = sm + OFF_B1;
    float* sW2 = sm + OFF_W2;
    float* sA  = sm + OFF_A;

    const int tid = threadIdx.x;
    const int cta = blockIdx.x;

    // Phase-1 role: slice s1, 16 stage-1 gate-cols starting at u0 (all in one gate)
    const int s1    = cta >> 5;
    const int u0    = (cta & 31) * 16;
    const int gate1 = u0 >> 7;

    // Phase-2 role: gate g2, 128-col tile starting c20, 64-row K-chunk starting k20
    const int g2  = cta >> 5;
    const int r2  = cta & 31;
    const int c20 = (r2 >> 3) * 128;
    const int k20 = (r2 & 7) * 64;

    // Phase-3 role: one (b,c) pair per thread; 128*256 = 64*512 exactly
    const int p3  = cta * NTHR + tid;
    const int b3  = p3 >> 9;
    const int c3  = p3 & 511;
    const int ct3 = c3 >> 7;
    const int cl3 = c3 & 127;

    // ---- load persistent weights into SMEM (once) ----
    for (int i = tid; i < 192 * 16; i += NTHR) {
        int k = i >> 4, c = i & 15;
        sW1[i] = (k < 64) ? Ws[s1 * (64 * 512) + k * 512 + u0 + c]
                          : Us[s1 * (128 * 512) + (k - 64) * 512 + u0 + c];
    }
    if (tid < 16) sB1[tid] = biases[s1 * 512 + u0 + tid];
    for (int i = tid; i < 64 * 128; i += NTHR) {
        int k = i >> 7, c = i & 127;
        sW2[i] = Wc[(k20 + k) * 2048 + g2 * 512 + c20 + c];
    }

    g_h[p3] = 0.0f;                 // h0 = 0 (each thread owns one element)
    const float bci = bc[c3];
    const float bcf = bc[512 + c3];
    const float bcg = bc[1024 + c3];
    const float bco = bc[1536 + c3];
    float creg  = 0.0f;             // cell state lives in a register all 512 steps
    float hlast = 0.0f;

    gbar();                          // h0 zeros globally visible

    for (int t = 0; t < TSEQ; t++) {
        // ================= Phase 1: stage-1 block-diagonal GEMM =================
        // stage x_t and h slice, transposed: sA[k][b]
        for (int i = tid; i < 64 * 64; i += NTHR) {
            int b = i >> 6, k = i & 63;
            sA[k * LDB + b] = __ldg(&x[b * (TSEQ * 256) + t * 256 + s1 * 64 + k]);
        }
        for (int i = tid; i < 64 * 128; i += NTHR) {
            int b = i >> 7, k = i & 127;
            sA[(64 + k) * LDB + b] = __ldcg(&g_h[b * 512 + s1 * 128 + k]);
        }
        __syncthreads();
        {
            const int c1 = tid & 15;          // col within block
            const int b0 = (tid >> 4) * 4;    // 4 batches per thread
            unsigned long long accA = 0ULL, accB = 0ULL;
            #pragma unroll 4
            for (int k = 0; k < 192; k++) {
                const ulonglong2 a2 = *reinterpret_cast<const ulonglong2*>(&sA[k * LDB + b0]);
                const float w = sW1[k * 16 + c1];
                const unsigned long long wp = pk2(w, w);
                fma2(accA, a2.x, wp);
                fma2(accB, a2.y, wp);
            }
            float v0, v1, v2, v3;
            unp2(accA, v0, v1);
            unp2(accB, v2, v3);
            const float bias = sB1[c1];
            v0 += bias; v1 += bias; v2 += bias; v3 += bias;
            if (gate1 == 2) {                 // g-gate -> tanh, others sigmoid
                v0 = tanhe(v0); v1 = tanhe(v1); v2 = tanhe(v2); v3 = tanhe(v3);
            } else {
                v0 = sigf(v0);  v1 = sigf(v1);  v2 = sigf(v2);  v3 = sigf(v3);
            }
            const int col = s1 * 128 + ((u0 + c1) & 127);
            float* dst = &g_act[gate1 * (BB * 512) + col];
            __stcg(&dst[(b0 + 0) * 512], v0);
            __stcg(&dst[(b0 + 1) * 512], v1);
            __stcg(&dst[(b0 + 2) * 512], v2);
            __stcg(&dst[(b0 + 3) * 512], v3);
        }
        gbar();

        // ================= Phase 2: connector GEMM (K-split partials) =================
        for (int i = tid; i < 64 * 64; i += NTHR) {
            int b = i >> 6, k = i & 63;
            sA[k * LDB + b] = __ldcg(&g_act[g2 * (BB * 512) + b * 512 + k20 + k]);
        }
        __syncthreads();
        {
            const int cc = (tid & 15) * 8;     // 8 cols
            const int b0 = (tid >> 4) * 4;     // 4 batches
            unsigned long long acc[4][4];
            #pragma unroll
            for (int i = 0; i < 4; i++) {
                #pragma unroll
                for (int j = 0; j < 4; j++) acc[i][j] = 0ULL;
            }
            #pragma unroll 4
            for (int k = 0; k < 64; k++) {
                const ulonglong2* wrow = reinterpret_cast<const ulonglong2*>(&sW2[k * 128 + cc]);
                const ulonglong2 wA = wrow[0];
                const ulonglong2 wB = wrow[1];
                const float4 a4 = *reinterpret_cast<const float4*>(&sA[k * LDB + b0]);
                const unsigned long long a0 = pk2(a4.x, a4.x);
                const unsigned long long a1 = pk2(a4.y, a4.y);
                const unsigned long long a2 = pk2(a4.z, a4.z);
                const unsigned long long a3 = pk2(a4.w, a4.w);
                fma2(acc[0][0], a0, wA.x); fma2(acc[0][1], a0, wA.y);
                fma2(acc[0][2], a0, wB.x); fma2(acc[0][3], a0, wB.y);
                fma2(acc[1][0], a1, wA.x); fma2(acc[1][1], a1, wA.y);
                fma2(acc[1][2], a1, wB.x); fma2(acc[1][3], a1, wB.y);
                fma2(acc[2][0], a2, wA.x); fma2(acc[2][1], a2, wA.y);
                fma2(acc[2][2], a2, wB.x); fma2(acc[2][3], a2, wB.y);
                fma2(acc[3][0], a3, wA.x); fma2(acc[3][1], a3, wA.y);
                fma2(acc[3][2], a3, wB.x); fma2(acc[3][3], a3, wB.y);
            }
            float* pp = &g_part[cta * (BB * 128)];
            #pragma unroll
            for (int i = 0; i < 4; i++) {
                float q0, q1, q2, q3, q4, q5, q6, q7;
                unp2(acc[i][0], q0, q1);
                unp2(acc[i][1], q2, q3);
                unp2(acc[i][2], q4, q5);
                unp2(acc[i][3], q6, q7);
                float4* d = reinterpret_cast<float4*>(&pp[(b0 + i) * 128 + cc]);
                __stcg(d,     make_float4(q0, q1, q2, q3));
                __stcg(d + 1, make_float4(q4, q5, q6, q7));
            }
        }
        gbar();

        // ================= Phase 3: reduce partials + cell update =================
        {
            float a0 = 0.f, a1 = 0.f, a2 = 0.f, a3 = 0.f;
            const int base = b3 * 128 + cl3;
            #pragma unroll
            for (int kc = 0; kc < 8; kc++) {
                a0 += __ldcg(&g_part[(0 * 32 + ct3 * 8 + kc) * (BB * 128) + base]);
                a1 += __ldcg(&g_part[(1 * 32 + ct3 * 8 + kc) * (BB * 128) + base]);
                a2 += __ldcg(&g_part[(2 * 32 + ct3 * 8 + kc) * (BB * 128) + base]);
                a3 += __ldcg(&g_part[(3 * 32 + ct3 * 8 + kc) * (BB * 128) + base]);
            }
            const float iv = sigf(a0 + bci);
            const float fv = sigf(a1 + bcf);
            const float gv = tanhe(a2 + bcg);
            const float ov = sigf(a3 + bco);
            creg = fv * creg + iv * gv;
            const float hn = ov * tanhe(creg);
            hlast = hn;
            __stcg(&g_h[p3], hn);
            out[b3 * (TSEQ * 512) + t * 512 + c3] = hn;
        }
        gbar();
    }

    // final h_t and c_t
    out[16777216 + p3] = hlast;
    out[16777216 + 32768 + p3] = creg;
}

extern "C" void kernel_launch(void* const* d_in, const int* in_sizes, int n_in,
                              void* d_out, int out_size) {
    const float* x      = (const float*)d_in[0];
    const float* Ws     = (const float*)d_in[1];
    const float* Us     = (const float*)d_in[2];
    const float* biases = (const float*)d_in[3];
    const float* Wc     = (const float*)d_in[4];
    const float* bc     = (const float*)d_in[5];
    float* out = (float*)d_out;
    (void)in_sizes; (void)n_in; (void)out_size;

    cudaFuncSetAttribute(slstm_kernel, cudaFuncAttributeMaxDynamicSharedMemorySize,
                         SMEM_FLOATS * 4);
    slstm_kernel<<<NCTA, NTHR, SMEM_FLOATS * 4>>>(x, Ws, Us, biases, Wc, bc, out);
}